// round 1
// baseline (speedup 1.0000x reference)
#include <cuda_runtime.h>
#include <cuda_bf16.h>

#define NMASKS     128
#define W          1024
#define WORDS      32              // 32-bit words per packed row
#define TILE_ROWS  64
#define HALO_ROWS  (TILE_ROWS + 2)
#define TILES_PER_MASK (W / TILE_ROWS)   // 16
#define STRIDE     (WORDS + 2)     // guard word on each side

__device__ unsigned int g_area[NMASKS];
__device__ unsigned int g_conn[NMASKS];
__device__ unsigned int g_perim[NMASKS];

__global__ void zero_kernel() {
    int i = threadIdx.x;
    if (i < NMASKS) { g_area[i] = 0u; g_conn[i] = 0u; g_perim[i] = 0u; }
}

__device__ __forceinline__ void csa(unsigned a, unsigned b, unsigned c,
                                    unsigned &s, unsigned &cy) {
    unsigned t = a ^ b;
    s  = t ^ c;
    cy = (a & b) | (t & c);
}

__global__ __launch_bounds__(256, 4)
void prior_main_kernel(const float* __restrict__ masks) {
    // packed binary rows, bit k of word w = column 32*w + k; guard cols at [0] and [33]
    __shared__ unsigned int srows[HALO_ROWS][STRIDE];

    const int bid  = blockIdx.x;
    const int mask = bid >> 4;          // 16 tiles per mask
    const int tile = bid & 15;
    const int r0   = tile * TILE_ROWS;
    const float* __restrict__ base = masks + (size_t)mask * (size_t)(W * W);

    const int tid  = threadIdx.x;
    const int lane = tid & 31;
    const int wp   = tid >> 5;          // 8 warps

    // ---- pack phase: binarize 66 rows into bitmasks via ballot ----
    for (int k = wp; k < HALO_ROWS; k += 8) {
        int gr = r0 - 1 + k;
        if ((unsigned)gr >= (unsigned)W) {
            // out-of-image halo row: all zeros (incl. guards)
            srows[k][lane] = 0u;
            if (lane < 2) srows[k][32 + lane] = 0u;
        } else {
            const float* __restrict__ rowp = base + (size_t)gr * W;
            if (lane == 0) { srows[k][0] = 0u; srows[k][WORDS + 1] = 0u; }
            #pragma unroll
            for (int it = 0; it < WORDS; it++) {
                float v = rowp[it * 32 + lane];
                unsigned b = __ballot_sync(0xffffffffu, v > 0.0f);
                if (lane == 0) srows[k][it + 1] = b;
            }
        }
    }
    __syncthreads();

    // ---- compute phase: 64 rows x 32 words, 8 word-tasks per thread ----
    unsigned accA = 0, accC = 0, accP = 0;
    #pragma unroll
    for (int i = 0; i < 8; i++) {
        int id = tid + 256 * i;
        int w  = (id & 31) + 1;         // 1..32 (guards at 0, 33)
        int r  = id >> 5;               // 0..63 ; smem rows r, r+1, r+2

        unsigned topL = srows[r    ][w - 1], top = srows[r    ][w], topR = srows[r    ][w + 1];
        unsigned midL = srows[r + 1][w - 1], mid = srows[r + 1][w], midR = srows[r + 1][w + 1];
        unsigned botL = srows[r + 2][w - 1], bot = srows[r + 2][w], botR = srows[r + 2][w + 1];

        // align col-1 / col+1 neighbors to current bit positions
        unsigned tl = (top << 1) | (topL >> 31);
        unsigned tr = (top >> 1) | (topR << 31);
        unsigned ml = (mid << 1) | (midL >> 31);
        unsigned mr = (mid >> 1) | (midR << 31);
        unsigned bl = (bot << 1) | (botL >> 31);
        unsigned br = (bot >> 1) | (botR << 31);

        // CSA tree: per-bit neighbor count (0..8) as bitplanes b0..b3
        unsigned s1, c1, s2, c2, s3, c3;
        csa(tl, top, tr, s1, c1);
        csa(ml, mr, bl, s2, c2);
        csa(bot, br, s1, s3, c3);
        unsigned s4 = s2 ^ s3, c4 = s2 & s3;
        unsigned u1, v1;
        csa(c1, c2, c3, u1, v1);
        unsigned u2 = u1 ^ c4, v2 = u1 & c4;
        unsigned b0 = s4, b1 = u2, b2 = v1 ^ v2, b3 = v1 & v2;

        // area
        accA += __popc(mid);

        // connectivity = sum of nc over foreground pixels
        unsigned conn = __popc(b0 & mid) + 2u * __popc(b1 & mid)
                      + 4u * __popc(b2 & mid) + 8u * __popc(b3 & mid);
        // total nc over all pixels in word
        unsigned tot  = __popc(b0) + 2u * __popc(b1)
                      + 4u * __popc(b2) + 8u * __popc(b3);
        // perimeter = (bg: nc) + (fg: max(nc-4,0) = 4*b3 + c2present*(2*b1+b0))
        unsigned perim = (tot - conn)
                       + 4u * __popc(b3 & mid)
                       + 2u * __popc(b2 & b1 & mid)
                       +      __popc(b2 & b0 & mid);

        accC += conn;
        accP += perim;
    }

    // warp reduce (exact integer), one atomicAdd per warp per counter
    accA = __reduce_add_sync(0xffffffffu, accA);
    accC = __reduce_add_sync(0xffffffffu, accC);
    accP = __reduce_add_sync(0xffffffffu, accP);
    if (lane == 0) {
        atomicAdd(&g_area[mask],  accA);
        atomicAdd(&g_conn[mask],  accC);
        atomicAdd(&g_perim[mask], accP);
    }
}

__global__ void score_kernel(float* __restrict__ out) {
    int i = threadIdx.x;
    if (i >= NMASKS) return;
    float area  = (float)g_area[i];
    float conn  = (float)g_conn[i];
    float perim = (float)g_perim[i];

    float safe_area  = (area > 0.0f) ? area : 1.0f;
    float area_ratio = area / (float)(W * W);
    float area_score = (area_ratio >= 0.001f && area_ratio <= 0.5f) ? 1.0f : 0.1f;

    float comp_score = (conn > 0.0f)
        ? fminf(1.0f, 10.0f / (conn / safe_area + 1e-6f))
        : 0.1f;

    float par = perim / safe_area;
    float shape_score = (area > 0.0f)
        ? ((par <= 100.0f) ? 1.0f : fmaxf(0.1f, 100.0f / (par + 1e-6f)))
        : 0.1f;

    float validity = 0.4f * area_score + 0.3f * comp_score + 0.3f * shape_score;
    out[i] = fmaxf(0.05f, validity);
}

extern "C" void kernel_launch(void* const* d_in, const int* in_sizes, int n_in,
                              void* d_out, int out_size) {
    const float* masks = (const float*)d_in[0];
    float* out = (float*)d_out;
    (void)in_sizes; (void)n_in; (void)out_size;

    zero_kernel<<<1, NMASKS>>>();
    prior_main_kernel<<<NMASKS * TILES_PER_MASK, 256>>>(masks);
    score_kernel<<<1, NMASKS>>>(out);
}